// round 12
// baseline (speedup 1.0000x reference)
#include <cuda_runtime.h>
#include <cuda_fp16.h>

#define NMAX 100000
#define EMAX 3200000
#define F 64
#define GMAX 64
#define PAD 128        // bucket capacity per node (max realistic degree ~60)
#define PADSH 7

struct __align__(8) EdgeT { int s; __half2 w2; };    // weight pre-duplicated

// Scratch (device globals — no allocation allowed)
__device__ int   g_cnt_n[NMAX];                      // per-node fill cursor == degree
__device__ float g_scale[NMAX];                      // 1/(sum_w*(deg+1)), layer-1 byproduct
__device__ __align__(16) EdgeT g_csr[NMAX * PAD];    // padded buckets {src, (w,w)}
__device__ __align__(16) __half g_hf[NMAX * F];      // fp16 feature table
__device__ __align__(16) float  g_x[NMAX * F];       // gather out / GEMM in
__device__ __align__(16) float  g_h2[NMAX * F];      // layer-2 activations
__device__ __align__(16) float  g_pool[GMAX * F];
__device__ float g_cnt[GMAX];

__device__ __forceinline__ __half2 u2h2(unsigned u) {
    return *reinterpret_cast<__half2*>(&u);
}

// ---------------------------------------------------------------------------
// Fused prologue: zero cursors/pool and convert input to fp16 table
// ---------------------------------------------------------------------------
__global__ void k_prep(const float* __restrict__ in, int n, int g) {
    int i = blockIdx.x * blockDim.x + threadIdx.x;
    int total4 = n * 16;
    if (i < total4) {
        float4 v = reinterpret_cast<const float4*>(in)[i];
        __half2 lo = __floats2half2_rn(v.x, v.y);
        __half2 hi = __floats2half2_rn(v.z, v.w);
        uint2 pk;
        pk.x = *reinterpret_cast<unsigned*>(&lo);
        pk.y = *reinterpret_cast<unsigned*>(&hi);
        reinterpret_cast<uint2*>(g_hf)[i] = pk;
    }
    if (i < n) g_cnt_n[i] = 0;
    if (i < g * F) g_pool[i] = 0.f;
    if (i < g) g_cnt[i] = 0.f;
}

// ---------------------------------------------------------------------------
// Bucket fill: 8 edges per thread; weights duplicated into half2.
// Cursor atomic doubles as degree count.
// ---------------------------------------------------------------------------
__global__ void k_fill(const float* __restrict__ ew, const int* __restrict__ src,
                       const int* __restrict__ dst, int e8) {
    int i = blockIdx.x * blockDim.x + threadIdx.x;
    if (i >= e8) return;
    int4   sa = reinterpret_cast<const int4*>(src)[2 * i];
    int4   sb = reinterpret_cast<const int4*>(src)[2 * i + 1];
    int4   da = reinterpret_cast<const int4*>(dst)[2 * i];
    int4   db = reinterpret_cast<const int4*>(dst)[2 * i + 1];
    float4 wa = reinterpret_cast<const float4*>(ew)[2 * i];
    float4 wb = reinterpret_cast<const float4*>(ew)[2 * i + 1];

    int p0 = atomicAdd(&g_cnt_n[da.x], 1);
    int p1 = atomicAdd(&g_cnt_n[da.y], 1);
    int p2 = atomicAdd(&g_cnt_n[da.z], 1);
    int p3 = atomicAdd(&g_cnt_n[da.w], 1);
    int p4 = atomicAdd(&g_cnt_n[db.x], 1);
    int p5 = atomicAdd(&g_cnt_n[db.y], 1);
    int p6 = atomicAdd(&g_cnt_n[db.z], 1);
    int p7 = atomicAdd(&g_cnt_n[db.w], 1);

    EdgeT r;
    r.s = sa.x; r.w2 = __float2half2_rn(wa.x); g_csr[(da.x << PADSH) + p0] = r;
    r.s = sa.y; r.w2 = __float2half2_rn(wa.y); g_csr[(da.y << PADSH) + p1] = r;
    r.s = sa.z; r.w2 = __float2half2_rn(wa.z); g_csr[(da.z << PADSH) + p2] = r;
    r.s = sa.w; r.w2 = __float2half2_rn(wa.w); g_csr[(da.w << PADSH) + p3] = r;
    r.s = sb.x; r.w2 = __float2half2_rn(wb.x); g_csr[(db.x << PADSH) + p4] = r;
    r.s = sb.y; r.w2 = __float2half2_rn(wb.y); g_csr[(db.y << PADSH) + p5] = r;
    r.s = sb.z; r.w2 = __float2half2_rn(wb.z); g_csr[(db.z << PADSH) + p6] = r;
    r.s = sb.w; r.w2 = __float2half2_rn(wb.w); g_csr[(db.w << PADSH) + p7] = r;
}

// tail edges (e not divisible by 8)
__global__ void k_fill_tail(const float* __restrict__ ew, const int* __restrict__ src,
                            const int* __restrict__ dst, int lo, int e) {
    int i = lo + blockIdx.x * blockDim.x + threadIdx.x;
    if (i < e) {
        int d = dst[i];
        int pos = atomicAdd(&g_cnt_n[d], 1);
        EdgeT rec;
        rec.s = src[i];
        rec.w2 = __float2half2_rn(ew[i]);
        g_csr[(d << PADSH) + pos] = rec;
    }
}

// ---------------------------------------------------------------------------
// Gather: warp per dst node, 4 edges per slot via quarter-warps.
// Lane covers 8 features (uint4 = 8 halves, LDG.128). HFMA2 accumulation on
// 4 independent half2 accumulators, flushed to fp32 every 16 edges.
// FIRST: accumulate sum_w (hadd2 + flush), store g_scale = 1/(sum_w*(deg+1)).
//   x[node] = sc * sum_e w_e*h[src_e]  +  h[node] / (deg + 1)
// ---------------------------------------------------------------------------
template <bool FIRST>
__global__ void __launch_bounds__(256) k_gather(int n) {
    int w = (blockIdx.x * blockDim.x + threadIdx.x) >> 5;
    int l = threadIdx.x & 31;
    if (w >= n) return;

    int q = l >> 3;             // quarter 0..3: handles edges 4k+q
    int fl = l & 7;             // feature group: halves 8*fl .. 8*fl+7

    int cnt = g_cnt_n[w];
    const EdgeT* row = g_csr + (w << PADSH);
    const uint4* hh4 = reinterpret_cast<const uint4*>(g_hf);   // 8 per node row

    float fa[8];
    #pragma unroll
    for (int k = 0; k < 8; k++) fa[k] = 0.f;
    float sw = 0.f;

    const __half2 z2 = __float2half2_rn(0.f);

    int e = 0;
    // main loop: 16 edges per iteration (each lane: 4 edges of its quarter)
    for (; e + 16 <= cnt; e += 16) {
        __half2 acc0 = z2, acc1 = z2, acc2 = z2, acc3 = z2;
        __half2 swh = z2;

        EdgeT ed0 = row[e + q];
        EdgeT ed1 = row[e + 4 + q];
        uint4 f0 = hh4[ed0.s * 8 + fl];
        uint4 f1 = hh4[ed1.s * 8 + fl];
        acc0 = __hfma2(ed0.w2, u2h2(f0.x), acc0);
        acc1 = __hfma2(ed0.w2, u2h2(f0.y), acc1);
        acc2 = __hfma2(ed0.w2, u2h2(f0.z), acc2);
        acc3 = __hfma2(ed0.w2, u2h2(f0.w), acc3);
        acc0 = __hfma2(ed1.w2, u2h2(f1.x), acc0);
        acc1 = __hfma2(ed1.w2, u2h2(f1.y), acc1);
        acc2 = __hfma2(ed1.w2, u2h2(f1.z), acc2);
        acc3 = __hfma2(ed1.w2, u2h2(f1.w), acc3);

        EdgeT ed2 = row[e + 8 + q];
        EdgeT ed3 = row[e + 12 + q];
        uint4 f2 = hh4[ed2.s * 8 + fl];
        uint4 f3 = hh4[ed3.s * 8 + fl];
        acc0 = __hfma2(ed2.w2, u2h2(f2.x), acc0);
        acc1 = __hfma2(ed2.w2, u2h2(f2.y), acc1);
        acc2 = __hfma2(ed2.w2, u2h2(f2.z), acc2);
        acc3 = __hfma2(ed2.w2, u2h2(f2.w), acc3);
        acc0 = __hfma2(ed3.w2, u2h2(f3.x), acc0);
        acc1 = __hfma2(ed3.w2, u2h2(f3.y), acc1);
        acc2 = __hfma2(ed3.w2, u2h2(f3.z), acc2);
        acc3 = __hfma2(ed3.w2, u2h2(f3.w), acc3);

        if (FIRST) {
            swh = __hadd2(__hadd2(ed0.w2, ed1.w2), __hadd2(ed2.w2, ed3.w2));
            sw += __low2float(swh);
        }

        // flush to fp32
        float2 c0 = __half22float2(acc0);
        float2 c1 = __half22float2(acc1);
        float2 c2 = __half22float2(acc2);
        float2 c3 = __half22float2(acc3);
        fa[0] += c0.x; fa[1] += c0.y;
        fa[2] += c1.x; fa[3] += c1.y;
        fa[4] += c2.x; fa[5] += c2.y;
        fa[6] += c3.x; fa[7] += c3.y;
    }

    // remainder: fp32 per-edge (each lane walks its quarter's edges)
    for (int ee = e + q; ee < cnt; ee += 4) {
        EdgeT ed = row[ee];
        uint4 f = hh4[ed.s * 8 + fl];
        float wf = __low2float(ed.w2);
        float2 c0 = __half22float2(u2h2(f.x));
        float2 c1 = __half22float2(u2h2(f.y));
        float2 c2 = __half22float2(u2h2(f.z));
        float2 c3 = __half22float2(u2h2(f.w));
        fa[0] = fmaf(wf, c0.x, fa[0]); fa[1] = fmaf(wf, c0.y, fa[1]);
        fa[2] = fmaf(wf, c1.x, fa[2]); fa[3] = fmaf(wf, c1.y, fa[3]);
        fa[4] = fmaf(wf, c2.x, fa[4]); fa[5] = fmaf(wf, c2.y, fa[5]);
        fa[6] = fmaf(wf, c3.x, fa[6]); fa[7] = fmaf(wf, c3.y, fa[7]);
        if (FIRST) sw += wf;
    }

    // combine quarters: lanes 0-7 end up with the full sums
    #pragma unroll
    for (int k = 0; k < 8; k++) {
        fa[k] += __shfl_down_sync(0xffffffffu, fa[k], 16);
        fa[k] += __shfl_down_sync(0xffffffffu, fa[k], 8);
    }
    if (FIRST) {
        sw += __shfl_down_sync(0xffffffffu, sw, 16);
        sw += __shfl_down_sync(0xffffffffu, sw, 8);
    }

    if (l < 8) {
        float inv = 1.0f / ((float)cnt + 1.0f);
        float sc;
        if (FIRST) {
            sc = (cnt > 0) ? (inv / sw) : 0.f;
            if (l == 0) g_scale[w] = sc;
        } else {
            sc = g_scale[w];
        }

        uint4 hs = hh4[w * 8 + l];
        float2 s0 = __half22float2(u2h2(hs.x));
        float2 s1 = __half22float2(u2h2(hs.y));
        float2 s2 = __half22float2(u2h2(hs.z));
        float2 s3 = __half22float2(u2h2(hs.w));

        float4 o0, o1;
        o0.x = fmaf(fa[0], sc, s0.x * inv);
        o0.y = fmaf(fa[1], sc, s0.y * inv);
        o0.z = fmaf(fa[2], sc, s1.x * inv);
        o0.w = fmaf(fa[3], sc, s1.y * inv);
        o1.x = fmaf(fa[4], sc, s2.x * inv);
        o1.y = fmaf(fa[5], sc, s2.y * inv);
        o1.z = fmaf(fa[6], sc, s3.x * inv);
        o1.w = fmaf(fa[7], sc, s3.y * inv);
        reinterpret_cast<float4*>(g_x)[w * 16 + l * 2]     = o0;
        reinterpret_cast<float4*>(g_x)[w * 16 + l * 2 + 1] = o1;
    }
}

// ---------------------------------------------------------------------------
// Register-tiled GEMM: out = relu(x @ W + b). 64x64 tile, 128 threads.
// ---------------------------------------------------------------------------
template <bool OUT_HALF>
__global__ void __launch_bounds__(128) k_gemm(const float* __restrict__ x,
                                              const float* __restrict__ W,
                                              const float* __restrict__ b,
                                              float* __restrict__ out, int n) {
    __shared__ float xsT[F][F + 1];
    __shared__ float Ws[F][F];
    __shared__ float bs[F];

    int t = threadIdx.x;
    for (int i = t; i < F * F; i += 128) Ws[i >> 6][i & 63] = W[i];
    if (t < F) bs[t] = b[t];

    int base = blockIdx.x * 64;

    #pragma unroll
    for (int j = 0; j < 8; j++) {
        int f = t + 128 * j;
        int nl = f >> 4;
        int k4 = f & 15;
        int gn = base + nl;
        float4 v = make_float4(0.f, 0.f, 0.f, 0.f);
        if (gn < n) v = reinterpret_cast<const float4*>(x)[gn * 16 + k4];
        xsT[k4 * 4 + 0][nl] = v.x;
        xsT[k4 * 4 + 1][nl] = v.y;
        xsT[k4 * 4 + 2][nl] = v.z;
        xsT[k4 * 4 + 3][nl] = v.w;
    }
    __syncthreads();

    int ng = t & 15;
    int cg = t >> 4;

    float acc[4][8];
    #pragma unroll
    for (int i = 0; i < 4; i++)
        #pragma unroll
        for (int j = 0; j < 8; j++) acc[i][j] = bs[cg * 8 + j];

    #pragma unroll 8
    for (int k = 0; k < F; k++) {
        float xf[4];
        #pragma unroll
        for (int i = 0; i < 4; i++) xf[i] = xsT[k][ng * 4 + i];
        float4 wa = *reinterpret_cast<float4*>(&Ws[k][cg * 8]);
        float4 wb = *reinterpret_cast<float4*>(&Ws[k][cg * 8 + 4]);
        #pragma unroll
        for (int i = 0; i < 4; i++) {
            acc[i][0] = fmaf(xf[i], wa.x, acc[i][0]);
            acc[i][1] = fmaf(xf[i], wa.y, acc[i][1]);
            acc[i][2] = fmaf(xf[i], wa.z, acc[i][2]);
            acc[i][3] = fmaf(xf[i], wa.w, acc[i][3]);
            acc[i][4] = fmaf(xf[i], wb.x, acc[i][4]);
            acc[i][5] = fmaf(xf[i], wb.y, acc[i][5]);
            acc[i][6] = fmaf(xf[i], wb.z, acc[i][6]);
            acc[i][7] = fmaf(xf[i], wb.w, acc[i][7]);
        }
    }

    #pragma unroll
    for (int i = 0; i < 4; i++) {
        int gn = base + ng * 4 + i;
        if (gn >= n) continue;
        if (OUT_HALF) {
            __half2 h0 = __floats2half2_rn(fmaxf(acc[i][0], 0.f), fmaxf(acc[i][1], 0.f));
            __half2 h1 = __floats2half2_rn(fmaxf(acc[i][2], 0.f), fmaxf(acc[i][3], 0.f));
            __half2 h2 = __floats2half2_rn(fmaxf(acc[i][4], 0.f), fmaxf(acc[i][5], 0.f));
            __half2 h3 = __floats2half2_rn(fmaxf(acc[i][6], 0.f), fmaxf(acc[i][7], 0.f));
            uint4 pk;
            pk.x = *reinterpret_cast<unsigned*>(&h0);
            pk.y = *reinterpret_cast<unsigned*>(&h1);
            pk.z = *reinterpret_cast<unsigned*>(&h2);
            pk.w = *reinterpret_cast<unsigned*>(&h3);
            reinterpret_cast<uint4*>(g_hf)[gn * 8 + cg] = pk;
        } else {
            float4 o0, o1;
            o0.x = fmaxf(acc[i][0], 0.f); o0.y = fmaxf(acc[i][1], 0.f);
            o0.z = fmaxf(acc[i][2], 0.f); o0.w = fmaxf(acc[i][3], 0.f);
            o1.x = fmaxf(acc[i][4], 0.f); o1.y = fmaxf(acc[i][5], 0.f);
            o1.z = fmaxf(acc[i][6], 0.f); o1.w = fmaxf(acc[i][7], 0.f);
            reinterpret_cast<float4*>(out)[gn * 16 + cg * 2]     = o0;
            reinterpret_cast<float4*>(out)[gn * 16 + cg * 2 + 1] = o1;
        }
    }
}

// ---------------------------------------------------------------------------
// Graph pooling: graph_ids sorted -> register run accumulation per warp
// ---------------------------------------------------------------------------
__global__ void k_pool(const float* __restrict__ h, const int* __restrict__ gid, int n) {
    int wid = (blockIdx.x * blockDim.x + threadIdx.x) >> 5;
    int lane = threadIdx.x & 31;
    int nwarps = (gridDim.x * blockDim.x) >> 5;
    int chunk = (n + nwarps - 1) / nwarps;
    int start = wid * chunk;
    int end = min(start + chunk, n);
    if (start >= end) return;

    int cur = -1;
    float s0 = 0.f, s1 = 0.f, c = 0.f;
    for (int node = start; node < end; node++) {
        int g = gid[node];
        if (g != cur) {
            if (cur >= 0) {
                atomicAdd(&g_pool[cur * F + lane], s0);
                atomicAdd(&g_pool[cur * F + lane + 32], s1);
                if (lane == 0) atomicAdd(&g_cnt[cur], c);
            }
            cur = g; s0 = s1 = 0.f; c = 0.f;
        }
        s0 += h[node * F + lane];
        s1 += h[node * F + lane + 32];
        c += 1.f;
    }
    if (cur >= 0) {
        atomicAdd(&g_pool[cur * F + lane], s0);
        atomicAdd(&g_pool[cur * F + lane + 32], s1);
        if (lane == 0) atomicAdd(&g_cnt[cur], c);
    }
}

// ---------------------------------------------------------------------------
__global__ void k_final(const float* __restrict__ Wc, const float* __restrict__ bc,
                        float* __restrict__ out, int g) {
    int t = threadIdx.x;
    if (t >= g * 2) return;
    int gi = t >> 1;
    int c = t & 1;
    float inv = 1.0f / fmaxf(g_cnt[gi], 1.0f);
    float s = bc[c];
    #pragma unroll
    for (int f = 0; f < F; f++)
        s = fmaf(g_pool[gi * F + f] * inv, Wc[f * 2 + c], s);
    out[t] = s;
}

// ---------------------------------------------------------------------------
extern "C" void kernel_launch(void* const* d_in, const int* in_sizes, int n_in,
                              void* d_out, int out_size) {
    const float* in_feat = (const float*)d_in[0];
    const float* ew      = (const float*)d_in[1];
    const float* W1      = (const float*)d_in[2];
    const float* b1      = (const float*)d_in[3];
    const float* W2      = (const float*)d_in[4];
    const float* b2      = (const float*)d_in[5];
    const float* Wc      = (const float*)d_in[6];
    const float* bc      = (const float*)d_in[7];
    const int*   src     = (const int*)d_in[8];
    const int*   dst     = (const int*)d_in[9];
    const int*   gid     = (const int*)d_in[10];

    int n = in_sizes[0] / F;
    int e = in_sizes[1];
    int g = out_size / 2;

    void *p_x = nullptr, *p_h2 = nullptr;
    cudaGetSymbolAddress(&p_x, g_x);
    cudaGetSymbolAddress(&p_h2, g_h2);
    float* xbuf = (float*)p_x;
    float* h2 = (float*)p_h2;

    int e8 = e >> 3;
    int nwb = (n * 32 + 255) / 256;     // warp-per-node
    int tiles = (n + 63) / 64;

    // prologue: fused zero+cvt, then fill buckets
    k_prep<<<(n * 16 + 255) / 256, 256>>>(in_feat, n, g);
    k_fill<<<(e8 + 255) / 256, 256>>>(ew, src, dst, e8);
    if (e & 7)
        k_fill_tail<<<1, 256>>>(ew, src, dst, e8 * 8, e);

    // layer 1 (computes + stores per-node scale; GEMM writes fp16 h1 into g_hf)
    k_gather<true><<<nwb, 256>>>(n);
    k_gemm<true><<<tiles, 128>>>(xbuf, W1, b1, nullptr, n);
    // layer 2 (reuses stored scale; GEMM writes fp32 h2)
    k_gather<false><<<nwb, 256>>>(n);
    k_gemm<false><<<tiles, 128>>>(xbuf, W2, b2, h2, n);

    // pooling + classifier
    k_pool<<<512, 256>>>(h2, gid, n);
    k_final<<<1, 128>>>(Wc, bc, (float*)d_out, g);
}

// round 13
// speedup vs baseline: 1.1240x; 1.1240x over previous
#include <cuda_runtime.h>
#include <cuda_fp16.h>

#define NMAX 100000
#define EMAX 3200000
#define F 64
#define GMAX 64
#define PAD 128        // bucket capacity per node (max realistic degree ~60)
#define PADSH 7

struct __align__(8) EdgeT { int s; float w; };

// Scratch (device globals — no allocation allowed)
__device__ int   g_cnt_n[NMAX];                      // per-node fill cursor == degree
__device__ float g_scale[NMAX];                      // 1/(sum_w*(deg+1)), layer-1 byproduct
__device__ __align__(16) EdgeT g_csr[NMAX * PAD];    // padded buckets {src, w}
__device__ __align__(16) __half g_hf[NMAX * F];      // fp16 table A (H0 / h1 / h2)
__device__ __align__(16) __half g_y[NMAX * F];       // fp16 table B (Y = H@W)
__device__ __align__(16) float  g_pool[GMAX * F];
__device__ float g_cnt[GMAX];

__device__ __forceinline__ __half2 u2h2(unsigned u) {
    return *reinterpret_cast<__half2*>(&u);
}

// ---------------------------------------------------------------------------
// Fused prologue: zero cursors/pool and convert input to fp16 table
// ---------------------------------------------------------------------------
__global__ void k_prep(const float* __restrict__ in, int n, int g) {
    int i = blockIdx.x * blockDim.x + threadIdx.x;
    int total4 = n * 16;
    if (i < total4) {
        float4 v = reinterpret_cast<const float4*>(in)[i];
        __half2 lo = __floats2half2_rn(v.x, v.y);
        __half2 hi = __floats2half2_rn(v.z, v.w);
        uint2 pk;
        pk.x = *reinterpret_cast<unsigned*>(&lo);
        pk.y = *reinterpret_cast<unsigned*>(&hi);
        reinterpret_cast<uint2*>(g_hf)[i] = pk;
    }
    if (i < n) g_cnt_n[i] = 0;
    if (i < g * F) g_pool[i] = 0.f;
    if (i < g) g_cnt[i] = 0.f;
}

// ---------------------------------------------------------------------------
// Bucket fill: 8 edges per thread. Cursor atomic doubles as degree count.
// ---------------------------------------------------------------------------
__global__ void k_fill(const float* __restrict__ ew, const int* __restrict__ src,
                       const int* __restrict__ dst, int e8) {
    int i = blockIdx.x * blockDim.x + threadIdx.x;
    if (i >= e8) return;
    int4   sa = reinterpret_cast<const int4*>(src)[2 * i];
    int4   sb = reinterpret_cast<const int4*>(src)[2 * i + 1];
    int4   da = reinterpret_cast<const int4*>(dst)[2 * i];
    int4   db = reinterpret_cast<const int4*>(dst)[2 * i + 1];
    float4 wa = reinterpret_cast<const float4*>(ew)[2 * i];
    float4 wb = reinterpret_cast<const float4*>(ew)[2 * i + 1];

    int p0 = atomicAdd(&g_cnt_n[da.x], 1);
    int p1 = atomicAdd(&g_cnt_n[da.y], 1);
    int p2 = atomicAdd(&g_cnt_n[da.z], 1);
    int p3 = atomicAdd(&g_cnt_n[da.w], 1);
    int p4 = atomicAdd(&g_cnt_n[db.x], 1);
    int p5 = atomicAdd(&g_cnt_n[db.y], 1);
    int p6 = atomicAdd(&g_cnt_n[db.z], 1);
    int p7 = atomicAdd(&g_cnt_n[db.w], 1);

    EdgeT r;
    r.s = sa.x; r.w = wa.x; g_csr[(da.x << PADSH) + p0] = r;
    r.s = sa.y; r.w = wa.y; g_csr[(da.y << PADSH) + p1] = r;
    r.s = sa.z; r.w = wa.z; g_csr[(da.z << PADSH) + p2] = r;
    r.s = sa.w; r.w = wa.w; g_csr[(da.w << PADSH) + p3] = r;
    r.s = sb.x; r.w = wb.x; g_csr[(db.x << PADSH) + p4] = r;
    r.s = sb.y; r.w = wb.y; g_csr[(db.y << PADSH) + p5] = r;
    r.s = sb.z; r.w = wb.z; g_csr[(db.z << PADSH) + p6] = r;
    r.s = sb.w; r.w = wb.w; g_csr[(db.w << PADSH) + p7] = r;
}

// tail edges (e not divisible by 8)
__global__ void k_fill_tail(const float* __restrict__ ew, const int* __restrict__ src,
                            const int* __restrict__ dst, int lo, int e) {
    int i = lo + blockIdx.x * blockDim.x + threadIdx.x;
    if (i < e) {
        int d = dst[i];
        int pos = atomicAdd(&g_cnt_n[d], 1);
        EdgeT rec;
        rec.s = src[i];
        rec.w = ew[i];
        g_csr[(d << PADSH) + pos] = rec;
    }
}

// ---------------------------------------------------------------------------
// Dense table GEMM: Y = X @ W (fp16 in, fp16 out, NO bias/relu — those move
// into the gather epilogue by linearity). 64x64 tile, 128 threads,
// 4 nodes x 8 cols per thread, fp32 math.
// ---------------------------------------------------------------------------
__global__ void __launch_bounds__(128) k_gemm(const __half* __restrict__ x,
                                              const float* __restrict__ W,
                                              __half* __restrict__ y, int n) {
    __shared__ float xsT[F][F + 1];   // [k][node]
    __shared__ float Ws[F][F];        // [k][col]

    int t = threadIdx.x;
    for (int i = t; i < F * F; i += 128) Ws[i >> 6][i & 63] = W[i];

    int base = blockIdx.x * 64;
    const uint4* xh = reinterpret_cast<const uint4*>(x);  // 8 halves; 8 per node row

    #pragma unroll
    for (int j = 0; j < 4; j++) {
        int f = t + 128 * j;      // 0..511
        int nl = f >> 3;          // local node 0..63
        int k8 = f & 7;           // uint4 slot (features 8*k8..8*k8+7)
        int gn = base + nl;
        uint4 v = make_uint4(0u, 0u, 0u, 0u);
        if (gn < n) v = xh[gn * 8 + k8];
        float2 c0 = __half22float2(u2h2(v.x));
        float2 c1 = __half22float2(u2h2(v.y));
        float2 c2 = __half22float2(u2h2(v.z));
        float2 c3 = __half22float2(u2h2(v.w));
        xsT[k8 * 8 + 0][nl] = c0.x;
        xsT[k8 * 8 + 1][nl] = c0.y;
        xsT[k8 * 8 + 2][nl] = c1.x;
        xsT[k8 * 8 + 3][nl] = c1.y;
        xsT[k8 * 8 + 4][nl] = c2.x;
        xsT[k8 * 8 + 5][nl] = c2.y;
        xsT[k8 * 8 + 6][nl] = c3.x;
        xsT[k8 * 8 + 7][nl] = c3.y;
    }
    __syncthreads();

    int ng = t & 15;    // local nodes ng*4 .. ng*4+3
    int cg = t >> 4;    // cols cg*8 .. cg*8+7

    float acc[4][8];
    #pragma unroll
    for (int i = 0; i < 4; i++)
        #pragma unroll
        for (int j = 0; j < 8; j++) acc[i][j] = 0.f;

    #pragma unroll 8
    for (int k = 0; k < F; k++) {
        float xf[4];
        #pragma unroll
        for (int i = 0; i < 4; i++) xf[i] = xsT[k][ng * 4 + i];
        float4 wa = *reinterpret_cast<float4*>(&Ws[k][cg * 8]);
        float4 wb = *reinterpret_cast<float4*>(&Ws[k][cg * 8 + 4]);
        #pragma unroll
        for (int i = 0; i < 4; i++) {
            acc[i][0] = fmaf(xf[i], wa.x, acc[i][0]);
            acc[i][1] = fmaf(xf[i], wa.y, acc[i][1]);
            acc[i][2] = fmaf(xf[i], wa.z, acc[i][2]);
            acc[i][3] = fmaf(xf[i], wa.w, acc[i][3]);
            acc[i][4] = fmaf(xf[i], wb.x, acc[i][4]);
            acc[i][5] = fmaf(xf[i], wb.y, acc[i][5]);
            acc[i][6] = fmaf(xf[i], wb.z, acc[i][6]);
            acc[i][7] = fmaf(xf[i], wb.w, acc[i][7]);
        }
    }

    #pragma unroll
    for (int i = 0; i < 4; i++) {
        int gn = base + ng * 4 + i;
        if (gn >= n) continue;
        __half2 h0 = __floats2half2_rn(acc[i][0], acc[i][1]);
        __half2 h1 = __floats2half2_rn(acc[i][2], acc[i][3]);
        __half2 h2 = __floats2half2_rn(acc[i][4], acc[i][5]);
        __half2 h3 = __floats2half2_rn(acc[i][6], acc[i][7]);
        uint4 pk;
        pk.x = *reinterpret_cast<unsigned*>(&h0);
        pk.y = *reinterpret_cast<unsigned*>(&h1);
        pk.z = *reinterpret_cast<unsigned*>(&h2);
        pk.w = *reinterpret_cast<unsigned*>(&h3);
        reinterpret_cast<uint4*>(y)[gn * 8 + cg] = pk;
    }
}

// ---------------------------------------------------------------------------
// Gather on Y (R10 inner loop, unchanged): warp per dst node, 2 edges per
// iteration via half-warps, lane covers 4 features (uint2), fp32 FMA.
// Epilogue applies bias + relu (moved out of the GEMM by linearity) and
// writes the fp16 table for the next stage:
//   out[node] = relu( sc * sum_e w_e*Y[src_e] + Y[node]/(deg+1) + b )
// FIRST: accumulate sum_w, store g_scale[node] = 1/(sum_w*(deg+1)).
// ---------------------------------------------------------------------------
template <bool FIRST>
__global__ void __launch_bounds__(256) k_gather(const __half* __restrict__ ytab,
                                                const float* __restrict__ b,
                                                __half* __restrict__ out, int n) {
    int w = (blockIdx.x * blockDim.x + threadIdx.x) >> 5;
    int l = threadIdx.x & 31;
    if (w >= n) return;

    int half = l >> 4;          // 0: even edges, 1: odd edges
    int fl = l & 15;            // feature group: features 4*fl .. 4*fl+3

    int cnt = g_cnt_n[w];
    const EdgeT* row = g_csr + (w << PADSH);
    const uint2* hh2 = reinterpret_cast<const uint2*>(ytab);  // 4 halves; 16 per node

    float a0 = 0.f, a1 = 0.f, a2 = 0.f, a3 = 0.f, sw = 0.f;

    int s = 0;  // slot s covers edges 2s (half 0) and 2s+1 (half 1)
    for (; 2 * (s + 4) <= cnt; s += 4) {
        EdgeT ed[4];
        #pragma unroll
        for (int j = 0; j < 4; j++) ed[j] = row[2 * (s + j) + half];
        uint2 f[4];
        #pragma unroll
        for (int j = 0; j < 4; j++) f[j] = hh2[ed[j].s * 16 + fl];
        #pragma unroll
        for (int j = 0; j < 4; j++) {
            float2 lo = __half22float2(u2h2(f[j].x));
            float2 hi = __half22float2(u2h2(f[j].y));
            float ww = ed[j].w;
            a0 = fmaf(ww, lo.x, a0);
            a1 = fmaf(ww, lo.y, a1);
            a2 = fmaf(ww, hi.x, a2);
            a3 = fmaf(ww, hi.y, a3);
            if (FIRST) sw += ww;
        }
    }
    for (int e = 2 * s + half; e < cnt; e += 2) {
        EdgeT ed = row[e];
        uint2 f = hh2[ed.s * 16 + fl];
        float2 lo = __half22float2(u2h2(f.x));
        float2 hi = __half22float2(u2h2(f.y));
        float ww = ed.w;
        a0 = fmaf(ww, lo.x, a0);
        a1 = fmaf(ww, lo.y, a1);
        a2 = fmaf(ww, hi.x, a2);
        a3 = fmaf(ww, hi.y, a3);
        if (FIRST) sw += ww;
    }

    // combine halves: lanes 0-15 add lane l+16's accumulators
    a0 += __shfl_down_sync(0xffffffffu, a0, 16);
    a1 += __shfl_down_sync(0xffffffffu, a1, 16);
    a2 += __shfl_down_sync(0xffffffffu, a2, 16);
    a3 += __shfl_down_sync(0xffffffffu, a3, 16);
    if (FIRST) sw += __shfl_down_sync(0xffffffffu, sw, 16);

    if (l < 16) {
        float inv = 1.0f / ((float)cnt + 1.0f);
        float sc;
        if (FIRST) {
            sc = (cnt > 0) ? (inv / sw) : 0.f;
            if (l == 0) g_scale[w] = sc;
        } else {
            sc = g_scale[w];
        }

        uint2 yself = hh2[w * 16 + fl];
        float2 slo = __half22float2(u2h2(yself.x));
        float2 shi = __half22float2(u2h2(yself.y));
        float4 bv = reinterpret_cast<const float4*>(b)[fl];

        float o0 = fmaxf(fmaf(a0, sc, fmaf(slo.x, inv, bv.x)), 0.f);
        float o1 = fmaxf(fmaf(a1, sc, fmaf(slo.y, inv, bv.y)), 0.f);
        float o2 = fmaxf(fmaf(a2, sc, fmaf(shi.x, inv, bv.z)), 0.f);
        float o3 = fmaxf(fmaf(a3, sc, fmaf(shi.y, inv, bv.w)), 0.f);

        __half2 p0 = __floats2half2_rn(o0, o1);
        __half2 p1 = __floats2half2_rn(o2, o3);
        uint2 pk;
        pk.x = *reinterpret_cast<unsigned*>(&p0);
        pk.y = *reinterpret_cast<unsigned*>(&p1);
        reinterpret_cast<uint2*>(out)[w * 16 + fl] = pk;
    }
}

// ---------------------------------------------------------------------------
// Graph pooling on fp16 table: graph_ids sorted -> register run accumulation.
// Lane covers features 2l, 2l+1 via one half2 load per node.
// ---------------------------------------------------------------------------
__global__ void k_pool(const __half* __restrict__ h, const int* __restrict__ gid, int n) {
    int wid = (blockIdx.x * blockDim.x + threadIdx.x) >> 5;
    int lane = threadIdx.x & 31;
    int nwarps = (gridDim.x * blockDim.x) >> 5;
    int chunk = (n + nwarps - 1) / nwarps;
    int start = wid * chunk;
    int end = min(start + chunk, n);
    if (start >= end) return;

    const unsigned* hp = reinterpret_cast<const unsigned*>(h);  // half2; 32 per node

    int cur = -1;
    float s0 = 0.f, s1 = 0.f, c = 0.f;
    for (int node = start; node < end; node++) {
        int g = gid[node];
        if (g != cur) {
            if (cur >= 0) {
                atomicAdd(&g_pool[cur * F + 2 * lane], s0);
                atomicAdd(&g_pool[cur * F + 2 * lane + 1], s1);
                if (lane == 0) atomicAdd(&g_cnt[cur], c);
            }
            cur = g; s0 = s1 = 0.f; c = 0.f;
        }
        float2 v = __half22float2(u2h2(hp[node * 32 + lane]));
        s0 += v.x;
        s1 += v.y;
        c += 1.f;
    }
    if (cur >= 0) {
        atomicAdd(&g_pool[cur * F + 2 * lane], s0);
        atomicAdd(&g_pool[cur * F + 2 * lane + 1], s1);
        if (lane == 0) atomicAdd(&g_cnt[cur], c);
    }
}

// ---------------------------------------------------------------------------
__global__ void k_final(const float* __restrict__ Wc, const float* __restrict__ bc,
                        float* __restrict__ out, int g) {
    int t = threadIdx.x;
    if (t >= g * 2) return;
    int gi = t >> 1;
    int c = t & 1;
    float inv = 1.0f / fmaxf(g_cnt[gi], 1.0f);
    float s = bc[c];
    #pragma unroll
    for (int f = 0; f < F; f++)
        s = fmaf(g_pool[gi * F + f] * inv, Wc[f * 2 + c], s);
    out[t] = s;
}

// ---------------------------------------------------------------------------
extern "C" void kernel_launch(void* const* d_in, const int* in_sizes, int n_in,
                              void* d_out, int out_size) {
    const float* in_feat = (const float*)d_in[0];
    const float* ew      = (const float*)d_in[1];
    const float* W1      = (const float*)d_in[2];
    const float* b1      = (const float*)d_in[3];
    const float* W2      = (const float*)d_in[4];
    const float* b2      = (const float*)d_in[5];
    const float* Wc      = (const float*)d_in[6];
    const float* bc      = (const float*)d_in[7];
    const int*   src     = (const int*)d_in[8];
    const int*   dst     = (const int*)d_in[9];
    const int*   gid     = (const int*)d_in[10];

    int n = in_sizes[0] / F;
    int e = in_sizes[1];
    int g = out_size / 2;

    void *p_hf = nullptr, *p_y = nullptr;
    cudaGetSymbolAddress(&p_hf, g_hf);
    cudaGetSymbolAddress(&p_y, g_y);
    __half* hf = (__half*)p_hf;
    __half* yb = (__half*)p_y;

    int e8 = e >> 3;
    int nwb = (n * 32 + 255) / 256;     // warp-per-node
    int tiles = (n + 63) / 64;

    // prologue: fused zero+cvt, then fill buckets
    k_prep<<<(n * 16 + 255) / 256, 256>>>(in_feat, n, g);
    k_fill<<<(e8 + 255) / 256, 256>>>(ew, src, dst, e8);
    if (e & 7)
        k_fill_tail<<<1, 256>>>(ew, src, dst, e8 * 8, e);

    // layer 1: Y1 = H0@W1, then gather (bias+relu fused) -> h1 (fp16, into g_hf)
    k_gemm<<<tiles, 128>>>(hf, W1, yb, n);
    k_gather<true><<<nwb, 256>>>(yb, b1, hf, n);
    // layer 2: Y2 = h1@W2, then gather -> h2 (fp16, into g_hf)
    k_gemm<<<tiles, 128>>>(hf, W2, yb, n);
    k_gather<false><<<nwb, 256>>>(yb, b2, hf, n);

    // pooling + classifier
    k_pool<<<512, 256>>>(hf, gid, n);
    k_final<<<1, 128>>>(Wc, bc, (float*)d_out, g);
}

// round 14
// speedup vs baseline: 1.3161x; 1.1709x over previous
#include <cuda_runtime.h>
#include <cuda_fp16.h>
#include <cstdint>

#define NMAX 100000
#define EMAX 3200000
#define F 64
#define GMAX 64
#define PAD 128        // bucket capacity per node (max realistic degree ~60)
#define PADSH 7
#define XSTR 72        // smem row stride in halves (144B: conflict-free ldmatrix)

struct __align__(8) EdgeT { int s; float w; };

// Scratch (device globals — no allocation allowed)
__device__ int   g_cnt_n[NMAX];                      // per-node fill cursor == degree
__device__ float g_scale[NMAX];                      // 1/(sum_w*(deg+1)), layer-1 byproduct
__device__ __align__(16) EdgeT g_csr[NMAX * PAD];    // padded buckets {src, w}
__device__ __align__(16) __half g_hf[NMAX * F];      // fp16 table A (H0 / h1 / h2)
__device__ __align__(16) __half g_y[NMAX * F];       // fp16 table B (Y = H@W)
__device__ __align__(16) float  g_pool[GMAX * F];
__device__ float g_cnt[GMAX];

__device__ __forceinline__ __half2 u2h2(unsigned u) {
    return *reinterpret_cast<__half2*>(&u);
}

// ---------------------------------------------------------------------------
// Fused prologue: zero cursors/pool and convert input to fp16 table
// ---------------------------------------------------------------------------
__global__ void k_prep(const float* __restrict__ in, int n, int g) {
    int i = blockIdx.x * blockDim.x + threadIdx.x;
    int total4 = n * 16;
    if (i < total4) {
        float4 v = reinterpret_cast<const float4*>(in)[i];
        __half2 lo = __floats2half2_rn(v.x, v.y);
        __half2 hi = __floats2half2_rn(v.z, v.w);
        uint2 pk;
        pk.x = *reinterpret_cast<unsigned*>(&lo);
        pk.y = *reinterpret_cast<unsigned*>(&hi);
        reinterpret_cast<uint2*>(g_hf)[i] = pk;
    }
    if (i < n) g_cnt_n[i] = 0;
    if (i < g * F) g_pool[i] = 0.f;
    if (i < g) g_cnt[i] = 0.f;
}

// ---------------------------------------------------------------------------
// Bucket fill: 8 edges per thread. Cursor atomic doubles as degree count.
// ---------------------------------------------------------------------------
__global__ void k_fill(const float* __restrict__ ew, const int* __restrict__ src,
                       const int* __restrict__ dst, int e8) {
    int i = blockIdx.x * blockDim.x + threadIdx.x;
    if (i >= e8) return;
    int4   sa = reinterpret_cast<const int4*>(src)[2 * i];
    int4   sb = reinterpret_cast<const int4*>(src)[2 * i + 1];
    int4   da = reinterpret_cast<const int4*>(dst)[2 * i];
    int4   db = reinterpret_cast<const int4*>(dst)[2 * i + 1];
    float4 wa = reinterpret_cast<const float4*>(ew)[2 * i];
    float4 wb = reinterpret_cast<const float4*>(ew)[2 * i + 1];

    int p0 = atomicAdd(&g_cnt_n[da.x], 1);
    int p1 = atomicAdd(&g_cnt_n[da.y], 1);
    int p2 = atomicAdd(&g_cnt_n[da.z], 1);
    int p3 = atomicAdd(&g_cnt_n[da.w], 1);
    int p4 = atomicAdd(&g_cnt_n[db.x], 1);
    int p5 = atomicAdd(&g_cnt_n[db.y], 1);
    int p6 = atomicAdd(&g_cnt_n[db.z], 1);
    int p7 = atomicAdd(&g_cnt_n[db.w], 1);

    EdgeT r;
    r.s = sa.x; r.w = wa.x; g_csr[(da.x << PADSH) + p0] = r;
    r.s = sa.y; r.w = wa.y; g_csr[(da.y << PADSH) + p1] = r;
    r.s = sa.z; r.w = wa.z; g_csr[(da.z << PADSH) + p2] = r;
    r.s = sa.w; r.w = wa.w; g_csr[(da.w << PADSH) + p3] = r;
    r.s = sb.x; r.w = wb.x; g_csr[(db.x << PADSH) + p4] = r;
    r.s = sb.y; r.w = wb.y; g_csr[(db.y << PADSH) + p5] = r;
    r.s = sb.z; r.w = wb.z; g_csr[(db.z << PADSH) + p6] = r;
    r.s = sb.w; r.w = wb.w; g_csr[(db.w << PADSH) + p7] = r;
}

// tail edges (e not divisible by 8)
__global__ void k_fill_tail(const float* __restrict__ ew, const int* __restrict__ src,
                            const int* __restrict__ dst, int lo, int e) {
    int i = lo + blockIdx.x * blockDim.x + threadIdx.x;
    if (i < e) {
        int d = dst[i];
        int pos = atomicAdd(&g_cnt_n[d], 1);
        EdgeT rec;
        rec.s = src[i];
        rec.w = ew[i];
        g_csr[(d << PADSH) + pos] = rec;
    }
}

// ---------------------------------------------------------------------------
// Tensor-core GEMM: Y = X @ W (fp16 in, fp16 out, fp32 accum, no bias/relu).
// 64x64 tile, 128 threads (4 warps x 16 rows). mma.sync m16n8k16.
// ---------------------------------------------------------------------------
__global__ void __launch_bounds__(128) k_gemm(const __half* __restrict__ x,
                                              const float* __restrict__ W,
                                              __half* __restrict__ y, int n) {
    __shared__ __half Xs[64 * XSTR];
    __shared__ __half Wsm[64 * XSTR];

    int t = threadIdx.x;
    int lane = t & 31;
    int warp = t >> 5;
    int base = blockIdx.x * 64;

    // load X tile (raw fp16, zero-padded past n)
    const uint4* xh = reinterpret_cast<const uint4*>(x);
    #pragma unroll
    for (int j = 0; j < 4; j++) {
        int f = t + 128 * j;      // 0..511
        int nl = f >> 3;          // local node 0..63
        int k8 = f & 7;           // 8-half slot
        int gn = base + nl;
        uint4 v = make_uint4(0u, 0u, 0u, 0u);
        if (gn < n) v = xh[gn * 8 + k8];
        *reinterpret_cast<uint4*>(&Xs[nl * XSTR + k8 * 8]) = v;
    }
    // load W (fp32 -> fp16)
    #pragma unroll
    for (int j = 0; j < 8; j++) {
        int f = t + 128 * j;      // 0..1023
        int k = f >> 4;           // W row
        int n4 = f & 15;          // float4 slot
        float4 wv = reinterpret_cast<const float4*>(W)[k * 16 + n4];
        __half2 lo = __floats2half2_rn(wv.x, wv.y);
        __half2 hi = __floats2half2_rn(wv.z, wv.w);
        uint2 pk;
        pk.x = *reinterpret_cast<unsigned*>(&lo);
        pk.y = *reinterpret_cast<unsigned*>(&hi);
        *reinterpret_cast<uint2*>(&Wsm[k * XSTR + n4 * 4]) = pk;
    }
    __syncthreads();

    float acc[8][4];
    #pragma unroll
    for (int nt = 0; nt < 8; nt++)
        #pragma unroll
        for (int i = 0; i < 4; i++) acc[nt][i] = 0.f;

    uint32_t xs_base = (uint32_t)__cvta_generic_to_shared(Xs);
    uint32_t ws_base = (uint32_t)__cvta_generic_to_shared(Wsm);

    // A address: lanes 0-15 rows @k0, lanes 16-31 rows @k0+8 (canonical m16k16)
    int arow = warp * 16 + (lane & 15);
    uint32_t a_off = xs_base + (uint32_t)(arow * XSTR * 2 + (lane >> 4) * 16);
    // B address: lanes 0-15 -> W rows k0..k0+15 (x2.trans uses lanes 0-15)
    int brow = lane & 15;

    #pragma unroll
    for (int kit = 0; kit < 4; kit++) {
        uint32_t a0, a1, a2, a3;
        asm volatile("ldmatrix.sync.aligned.m8n8.x4.shared.b16 {%0,%1,%2,%3}, [%4];"
                     : "=r"(a0), "=r"(a1), "=r"(a2), "=r"(a3)
                     : "r"(a_off + kit * 32));
        uint32_t b_base = ws_base + (uint32_t)((kit * 16 + brow) * XSTR * 2);
        #pragma unroll
        for (int nt = 0; nt < 8; nt++) {
            uint32_t b0, b1;
            asm volatile("ldmatrix.sync.aligned.m8n8.x2.trans.shared.b16 {%0,%1}, [%2];"
                         : "=r"(b0), "=r"(b1)
                         : "r"(b_base + nt * 16));
            asm volatile("mma.sync.aligned.m16n8k16.row.col.f32.f16.f16.f32 "
                         "{%0,%1,%2,%3}, {%4,%5,%6,%7}, {%8,%9}, {%0,%1,%2,%3};"
                         : "+f"(acc[nt][0]), "+f"(acc[nt][1]),
                           "+f"(acc[nt][2]), "+f"(acc[nt][3])
                         : "r"(a0), "r"(a1), "r"(a2), "r"(a3), "r"(b0), "r"(b1));
        }
    }

    // store D: c0,c1 -> (row, col..col+1); c2,c3 -> (row+8, ...)
    int drow = warp * 16 + (lane >> 2);
    int dcolh = (lane & 3);           // half2 index within 8-col tile
    #pragma unroll
    for (int nt = 0; nt < 8; nt++) {
        int col2 = nt * 4 + dcolh;    // half2 slot within the 32 half2 of a row
        int gn0 = base + drow;
        int gn1 = gn0 + 8;
        if (gn0 < n) {
            __half2 p = __floats2half2_rn(acc[nt][0], acc[nt][1]);
            reinterpret_cast<unsigned*>(y)[gn0 * 32 + col2] = *reinterpret_cast<unsigned*>(&p);
        }
        if (gn1 < n) {
            __half2 p = __floats2half2_rn(acc[nt][2], acc[nt][3]);
            reinterpret_cast<unsigned*>(y)[gn1 * 32 + col2] = *reinterpret_cast<unsigned*>(&p);
        }
    }
}

// ---------------------------------------------------------------------------
// Gather on Y (R10 inner loop): warp per dst node, 2 edges per iteration via
// half-warps, lane covers 4 features (uint2), fp32 FMA. Epilogue applies
// bias + relu and writes the fp16 table for the next stage:
//   out[node] = relu( sc * sum_e w_e*Y[src_e] + Y[node]/(deg+1) + b )
// FIRST: accumulate sum_w, store g_scale[node] = 1/(sum_w*(deg+1)).
// ---------------------------------------------------------------------------
template <bool FIRST>
__global__ void __launch_bounds__(256) k_gather(const __half* __restrict__ ytab,
                                                const float* __restrict__ b,
                                                __half* __restrict__ out, int n) {
    int w = (blockIdx.x * blockDim.x + threadIdx.x) >> 5;
    int l = threadIdx.x & 31;
    if (w >= n) return;

    int half = l >> 4;          // 0: even edges, 1: odd edges
    int fl = l & 15;            // feature group: features 4*fl .. 4*fl+3

    int cnt = g_cnt_n[w];
    const EdgeT* row = g_csr + (w << PADSH);
    const uint2* hh2 = reinterpret_cast<const uint2*>(ytab);  // 4 halves; 16 per node

    float a0 = 0.f, a1 = 0.f, a2 = 0.f, a3 = 0.f, sw = 0.f;

    int s = 0;  // slot s covers edges 2s (half 0) and 2s+1 (half 1)
    for (; 2 * (s + 4) <= cnt; s += 4) {
        EdgeT ed[4];
        #pragma unroll
        for (int j = 0; j < 4; j++) ed[j] = row[2 * (s + j) + half];
        uint2 f[4];
        #pragma unroll
        for (int j = 0; j < 4; j++) f[j] = hh2[ed[j].s * 16 + fl];
        #pragma unroll
        for (int j = 0; j < 4; j++) {
            float2 lo = __half22float2(u2h2(f[j].x));
            float2 hi = __half22float2(u2h2(f[j].y));
            float ww = ed[j].w;
            a0 = fmaf(ww, lo.x, a0);
            a1 = fmaf(ww, lo.y, a1);
            a2 = fmaf(ww, hi.x, a2);
            a3 = fmaf(ww, hi.y, a3);
            if (FIRST) sw += ww;
        }
    }
    for (int e = 2 * s + half; e < cnt; e += 2) {
        EdgeT ed = row[e];
        uint2 f = hh2[ed.s * 16 + fl];
        float2 lo = __half22float2(u2h2(f.x));
        float2 hi = __half22float2(u2h2(f.y));
        float ww = ed.w;
        a0 = fmaf(ww, lo.x, a0);
        a1 = fmaf(ww, lo.y, a1);
        a2 = fmaf(ww, hi.x, a2);
        a3 = fmaf(ww, hi.y, a3);
        if (FIRST) sw += ww;
    }

    // combine halves: lanes 0-15 add lane l+16's accumulators
    a0 += __shfl_down_sync(0xffffffffu, a0, 16);
    a1 += __shfl_down_sync(0xffffffffu, a1, 16);
    a2 += __shfl_down_sync(0xffffffffu, a2, 16);
    a3 += __shfl_down_sync(0xffffffffu, a3, 16);
    if (FIRST) sw += __shfl_down_sync(0xffffffffu, sw, 16);

    if (l < 16) {
        float inv = 1.0f / ((float)cnt + 1.0f);
        float sc;
        if (FIRST) {
            sc = (cnt > 0) ? (inv / sw) : 0.f;
            if (l == 0) g_scale[w] = sc;
        } else {
            sc = g_scale[w];
        }

        uint2 yself = hh2[w * 16 + fl];
        float2 slo = __half22float2(u2h2(yself.x));
        float2 shi = __half22float2(u2h2(yself.y));
        float4 bv = reinterpret_cast<const float4*>(b)[fl];

        float o0 = fmaxf(fmaf(a0, sc, fmaf(slo.x, inv, bv.x)), 0.f);
        float o1 = fmaxf(fmaf(a1, sc, fmaf(slo.y, inv, bv.y)), 0.f);
        float o2 = fmaxf(fmaf(a2, sc, fmaf(shi.x, inv, bv.z)), 0.f);
        float o3 = fmaxf(fmaf(a3, sc, fmaf(shi.y, inv, bv.w)), 0.f);

        __half2 p0 = __floats2half2_rn(o0, o1);
        __half2 p1 = __floats2half2_rn(o2, o3);
        uint2 pk;
        pk.x = *reinterpret_cast<unsigned*>(&p0);
        pk.y = *reinterpret_cast<unsigned*>(&p1);
        reinterpret_cast<uint2*>(out)[w * 16 + fl] = pk;
    }
}

// ---------------------------------------------------------------------------
// Graph pooling on fp16 table: graph_ids sorted -> register run accumulation.
// ---------------------------------------------------------------------------
__global__ void k_pool(const __half* __restrict__ h, const int* __restrict__ gid, int n) {
    int wid = (blockIdx.x * blockDim.x + threadIdx.x) >> 5;
    int lane = threadIdx.x & 31;
    int nwarps = (gridDim.x * blockDim.x) >> 5;
    int chunk = (n + nwarps - 1) / nwarps;
    int start = wid * chunk;
    int end = min(start + chunk, n);
    if (start >= end) return;

    const unsigned* hp = reinterpret_cast<const unsigned*>(h);  // half2; 32 per node

    int cur = -1;
    float s0 = 0.f, s1 = 0.f, c = 0.f;
    for (int node = start; node < end; node++) {
        int g = gid[node];
        if (g != cur) {
            if (cur >= 0) {
                atomicAdd(&g_pool[cur * F + 2 * lane], s0);
                atomicAdd(&g_pool[cur * F + 2 * lane + 1], s1);
                if (lane == 0) atomicAdd(&g_cnt[cur], c);
            }
            cur = g; s0 = s1 = 0.f; c = 0.f;
        }
        float2 v = __half22float2(u2h2(hp[node * 32 + lane]));
        s0 += v.x;
        s1 += v.y;
        c += 1.f;
    }
    if (cur >= 0) {
        atomicAdd(&g_pool[cur * F + 2 * lane], s0);
        atomicAdd(&g_pool[cur * F + 2 * lane + 1], s1);
        if (lane == 0) atomicAdd(&g_cnt[cur], c);
    }
}

// ---------------------------------------------------------------------------
__global__ void k_final(const float* __restrict__ Wc, const float* __restrict__ bc,
                        float* __restrict__ out, int g) {
    int t = threadIdx.x;
    if (t >= g * 2) return;
    int gi = t >> 1;
    int c = t & 1;
    float inv = 1.0f / fmaxf(g_cnt[gi], 1.0f);
    float s = bc[c];
    #pragma unroll
    for (int f = 0; f < F; f++)
        s = fmaf(g_pool[gi * F + f] * inv, Wc[f * 2 + c], s);
    out[t] = s;
}

// ---------------------------------------------------------------------------
extern "C" void kernel_launch(void* const* d_in, const int* in_sizes, int n_in,
                              void* d_out, int out_size) {
    const float* in_feat = (const float*)d_in[0];
    const float* ew      = (const float*)d_in[1];
    const float* W1      = (const float*)d_in[2];
    const float* b1      = (const float*)d_in[3];
    const float* W2      = (const float*)d_in[4];
    const float* b2      = (const float*)d_in[5];
    const float* Wc      = (const float*)d_in[6];
    const float* bc      = (const float*)d_in[7];
    const int*   src     = (const int*)d_in[8];
    const int*   dst     = (const int*)d_in[9];
    const int*   gid     = (const int*)d_in[10];

    int n = in_sizes[0] / F;
    int e = in_sizes[1];
    int g = out_size / 2;

    void *p_hf = nullptr, *p_y = nullptr;
    cudaGetSymbolAddress(&p_hf, g_hf);
    cudaGetSymbolAddress(&p_y, g_y);
    __half* hf = (__half*)p_hf;
    __half* yb = (__half*)p_y;

    int e8 = e >> 3;
    int nwb = (n * 32 + 255) / 256;     // warp-per-node
    int tiles = (n + 63) / 64;

    // prologue: fused zero+cvt, then fill buckets
    k_prep<<<(n * 16 + 255) / 256, 256>>>(in_feat, n, g);
    k_fill<<<(e8 + 255) / 256, 256>>>(ew, src, dst, e8);
    if (e & 7)
        k_fill_tail<<<1, 256>>>(ew, src, dst, e8 * 8, e);

    // layer 1: Y1 = H0@W1 (HMMA), then gather (bias+relu fused) -> h1 (fp16)
    k_gemm<<<tiles, 128>>>(hf, W1, yb, n);
    k_gather<true><<<nwb, 256>>>(yb, b1, hf, n);
    // layer 2: Y2 = h1@W2, then gather -> h2 (fp16)
    k_gemm<<<tiles, 128>>>(hf, W2, yb, n);
    k_gather<false><<<nwb, 256>>>(yb, b2, hf, n);

    // pooling + classifier
    k_pool<<<512, 256>>>(hf, gid, n);
    k_final<<<1, 128>>>(Wc, bc, (float*)d_out, g);
}